// round 10
// baseline (speedup 1.0000x reference)
#include <cuda_runtime.h>

#define NN 100000
#define NE 1600000
#define NPART 98   // ceil(NN/1024)

// ---------------- scratch (static device globals; no allocs) ----------------
__device__ int      g_cnt[NN];
__device__ int      g_off[NN + 1];
__device__ int      g_pos[NN];
__device__ int      g_part[NPART];
__device__ int      g_srcs[NE];
__device__ unsigned g_B0t[128 * 256];          // tf32, [n][k] transposed, k<128:Wl0, k>=128:Wr0
__device__ unsigned g_B1t[128 * 128];          // tf32, [j][k]; j<64:Wl1 col, j>=64:Wr1 col
__device__ float    g_m0[(size_t)NN * 128];    // mean-aggregated x
__device__ float    g_h[(size_t)NN * 128];     // relu'd layer-0 output
__device__ float    g_yz1[(size_t)NN * 128];   // y1 = cols 0..63, z1 = cols 64..127

// ---------------- tf32 mma helpers ----------------
__device__ __forceinline__ unsigned f2tf32(float f) {
    unsigned r;
    asm("cvt.rna.tf32.f32 %0, %1;" : "=r"(r) : "f"(f));
    return r;
}
__device__ __forceinline__ unsigned sptr(const void* p) {
    return (unsigned)__cvta_generic_to_shared(p);
}
#define LDSM4(R, addr)                                                              \
    asm volatile("ldmatrix.sync.aligned.m8n8.x4.shared.b16 {%0,%1,%2,%3}, [%4];"    \
                 : "=r"((R)[0]), "=r"((R)[1]), "=r"((R)[2]), "=r"((R)[3])           \
                 : "r"(addr))
__device__ __forceinline__ void mma_tf32(float* c, const unsigned* a, unsigned b0, unsigned b1) {
    asm volatile(
        "mma.sync.aligned.m16n8k8.row.col.f32.tf32.tf32.f32 "
        "{%0,%1,%2,%3},{%4,%5,%6,%7},{%8,%9},{%0,%1,%2,%3};"
        : "+f"(c[0]), "+f"(c[1]), "+f"(c[2]), "+f"(c[3])
        : "r"(a[0]), "r"(a[1]), "r"(a[2]), "r"(a[3]), "r"(b0), "r"(b1));
}

// ---------------- CSR build ----------------
__global__ void k_zero() {
    int i = blockIdx.x * blockDim.x + threadIdx.x;
    if (i < NN) g_cnt[i] = 0;
}

// edge_index is int32 (JAX x64 disabled).
__global__ void k_count(const int* __restrict__ ei) {
    int e = blockIdx.x * blockDim.x + threadIdx.x;
    if (e < NE) {
        unsigned d = (unsigned)ei[NE + e];
        if (d < NN) atomicAdd(&g_cnt[d], 1);
    }
}

__global__ void k_scanA() {  // grid NPART, block 1024: block sums
    int i = blockIdx.x * 1024 + threadIdx.x;
    int v = (i < NN) ? g_cnt[i] : 0;
    __shared__ int ws[32];
    int lane = threadIdx.x & 31, w = threadIdx.x >> 5;
#pragma unroll
    for (int d = 16; d; d >>= 1) v += __shfl_down_sync(~0u, v, d);
    if (!lane) ws[w] = v;
    __syncthreads();
    if (!w) {
        int s = ws[lane];
#pragma unroll
        for (int d = 16; d; d >>= 1) s += __shfl_down_sync(~0u, s, d);
        if (!lane) g_part[blockIdx.x] = s;
    }
}

__global__ void k_scanB() {  // 1 block / 128 threads: exclusive scan of NPART partials
    int t = threadIdx.x;
    int lane = t & 31, w = t >> 5;
    int c = (t < NPART) ? g_part[t] : 0;
    int v = c;
#pragma unroll
    for (int d = 1; d < 32; d <<= 1) {
        int u = __shfl_up_sync(~0u, v, d);
        if (lane >= d) v += u;
    }
    __shared__ int ws[4];
    if (lane == 31) ws[w] = v;
    __syncthreads();
    int add = 0;
#pragma unroll
    for (int i = 0; i < 4; i++)
        if (i < w) add += ws[i];
    int incl = v + add;
    if (t < NPART) g_part[t] = incl - c;
    if (t == NPART - 1) g_off[NN] = incl;
}

__global__ void k_scanC() {  // grid NPART, block 1024: local exclusive scan + offset
    int i = blockIdx.x * 1024 + threadIdx.x;
    int c = (i < NN) ? g_cnt[i] : 0;
    int v = c;
    int lane = threadIdx.x & 31, w = threadIdx.x >> 5;
#pragma unroll
    for (int d = 1; d < 32; d <<= 1) {
        int t = __shfl_up_sync(~0u, v, d);
        if (lane >= d) v += t;
    }
    __shared__ int ws[32];
    if (lane == 31) ws[w] = v;
    __syncthreads();
    if (!w) {
        int s = ws[lane];
#pragma unroll
        for (int d = 1; d < 32; d <<= 1) {
            int t = __shfl_up_sync(~0u, s, d);
            if (lane >= d) s += t;
        }
        ws[lane] = s;
    }
    __syncthreads();
    int excl = v - c + (w ? ws[w - 1] : 0) + g_part[blockIdx.x];
    if (i < NN) {
        g_off[i] = excl;
        g_pos[i] = excl;
    }
}

__global__ void k_scatter(const int* __restrict__ ei) {
    int e = blockIdx.x * blockDim.x + threadIdx.x;
    if (e < NE) {
        unsigned d = (unsigned)ei[NE + e];
        if (d < NN) {
            int p = atomicAdd(&g_pos[d], 1);
            unsigned s = (unsigned)ei[e];
            g_srcs[p] = (s < NN) ? (int)s : 0;
        }
    }
}

// ---------------- pack weights: transposed tf32 [n][k] ----------------
__global__ void k_pack(const float* __restrict__ Wl0, const float* __restrict__ Wr0,
                       const float* __restrict__ Wl1, const float* __restrict__ Wr1) {
    int i = blockIdx.x * blockDim.x + threadIdx.x;
    if (i < 128 * 256) {  // B0t[n*256 + k]
        int n = i >> 8, k = i & 255;
        float v = (k < 128) ? Wl0[k * 128 + n] : Wr0[(k - 128) * 128 + n];
        g_B0t[i] = f2tf32(v);
    }
    if (i < 128 * 128) {  // B1t[j*128 + k]
        int j = i >> 7, k = i & 127;
        float v = (j < 64) ? Wl1[k * 64 + j] : Wr1[k * 64 + (j - 64)];
        g_B1t[i] = f2tf32(v);
    }
}

// ---------------- input-space mean aggregation: m0 = mean(x[src]) ----------------
// warp per node; lane handles float4; 4-deep unrolled gather (MLP 4).
__global__ void k_aggx(const float* __restrict__ x) {
    int node = blockIdx.x * 8 + (threadIdx.x >> 5);
    int lane = threadIdx.x & 31;
    if (node >= NN) return;
    int beg = g_off[node], end = g_off[node + 1];
    float inv = 1.0f / (float)max(end - beg, 1);
    float4 a0 = make_float4(0.f, 0.f, 0.f, 0.f);
    float4 a1 = make_float4(0.f, 0.f, 0.f, 0.f);
    float4 a2 = make_float4(0.f, 0.f, 0.f, 0.f);
    float4 a3 = make_float4(0.f, 0.f, 0.f, 0.f);
    int e = beg;
    for (; e + 4 <= end; e += 4) {
        int s0 = g_srcs[e], s1 = g_srcs[e + 1], s2 = g_srcs[e + 2], s3 = g_srcs[e + 3];
        float4 v0 = *(const float4*)&x[(size_t)s0 * 128 + lane * 4];
        float4 v1 = *(const float4*)&x[(size_t)s1 * 128 + lane * 4];
        float4 v2 = *(const float4*)&x[(size_t)s2 * 128 + lane * 4];
        float4 v3 = *(const float4*)&x[(size_t)s3 * 128 + lane * 4];
        a0.x += v0.x; a0.y += v0.y; a0.z += v0.z; a0.w += v0.w;
        a1.x += v1.x; a1.y += v1.y; a1.z += v1.z; a1.w += v1.w;
        a2.x += v2.x; a2.y += v2.y; a2.z += v2.z; a2.w += v2.w;
        a3.x += v3.x; a3.y += v3.y; a3.z += v3.z; a3.w += v3.w;
    }
    for (; e < end; e++) {
        int s0 = g_srcs[e];
        float4 v0 = *(const float4*)&x[(size_t)s0 * 128 + lane * 4];
        a0.x += v0.x; a0.y += v0.y; a0.z += v0.z; a0.w += v0.w;
    }
    float4 r;
    r.x = (a0.x + a1.x + a2.x + a3.x) * inv;
    r.y = (a0.y + a1.y + a2.y + a3.y) * inv;
    r.z = (a0.z + a1.z + a2.z + a3.z) * inv;
    r.w = (a0.w + a1.w + a2.w + a3.w) * inv;
    *(float4*)&g_m0[(size_t)node * 128 + lane * 4] = r;
}

// ---------------- tf32 tensor-core GEMM v2 ----------------
// B resident in smem for the whole kernel; A double-buffered; 512 thr = 16 warps (4m x 4n).
// PHASE 0: C = concat(m0, x) @ B0t (K=256), epilogue bias+relu -> g_h
// PHASE 1: C = g_h @ B1t (K=128), plain fp32 store -> g_yz1
template <int PHASE>
__global__ __launch_bounds__(512) void k_gemm(const float* __restrict__ x,
                                              const float* __restrict__ bias) {
    const int K = (PHASE == 0) ? 256 : 128;
    const int KPAD = K + 4;
    extern __shared__ unsigned dsm[];
    unsigned* Bs = dsm;                       // [128][KPAD]
    unsigned* As = dsm + 128 * KPAD;          // [2][128][20]

    const unsigned* __restrict__ Bt = (PHASE == 0) ? g_B0t : g_B1t;

    int tid = threadIdx.x;
    int lane = tid & 31;
    int wid = tid >> 5;
    int warp_m = (wid & 3) * 32;
    int warp_n = (wid >> 2) * 32;
    int m0b = blockIdx.x * 128;

    // ---- load entire B tile once (coalesced along k) ----
    for (int idx = tid; idx < 128 * (K / 4); idx += 512) {
        int n = idx / (K / 4);
        int kq = (idx % (K / 4)) * 4;
        uint4 v = *(const uint4*)&Bt[n * K + kq];
        *(uint4*)&Bs[n * KPAD + kq] = v;
    }

    // ---- A tile fill (BK=16): thread -> (row = tid>>2, kq = (tid&3)*4) ----
    int aRow = tid >> 2;
    int aKq = (tid & 3) * 4;
    int grow = m0b + aRow;

    auto fillA = [&](int buf, int k0) {
        const float* __restrict__ A = (PHASE == 0) ? ((k0 < 128) ? g_m0 : x) : g_h;
        float4 av = make_float4(0.f, 0.f, 0.f, 0.f);
        if (grow < NN) av = *(const float4*)&A[(size_t)grow * 128 + (k0 & 127) + aKq];
        *(uint4*)&As[buf * 128 * 20 + aRow * 20 + aKq] =
            make_uint4(f2tf32(av.x), f2tf32(av.y), f2tf32(av.z), f2tf32(av.w));
    };

    float acc[2][4][4];
#pragma unroll
    for (int mi = 0; mi < 2; mi++)
#pragma unroll
        for (int ni = 0; ni < 4; ni++)
#pragma unroll
            for (int q = 0; q < 4; q++) acc[mi][ni][q] = 0.f;

    int g = lane >> 3, r = lane & 7;
    const int NT = K / 16;

    fillA(0, 0);
    __syncthreads();

    for (int t = 0; t < NT; t++) {
        if (t + 1 < NT) fillA((t + 1) & 1, (t + 1) * 16);
        int kb = t * 16;
        int abase = (t & 1) * 128 * 20;
#pragma unroll
        for (int ks2 = 0; ks2 < 2; ks2++) {
            int ks = ks2 * 8;
            unsigned aF[2][4], bF[2][4];
#pragma unroll
            for (int mi = 0; mi < 2; mi++) {
                int row = warp_m + mi * 16 + (g & 1) * 8 + r;
                int col = ks + (g >> 1) * 4;
                LDSM4(aF[mi], sptr(&As[abase + row * 20 + col]));
            }
#pragma unroll
            for (int nt = 0; nt < 2; nt++) {
                int row = warp_n + nt * 16 + (g >> 1) * 8 + r;
                int col = kb + ks + (g & 1) * 4;
                LDSM4(bF[nt], sptr(&Bs[row * KPAD + col]));
            }
#pragma unroll
            for (int mi = 0; mi < 2; mi++)
#pragma unroll
                for (int nt = 0; nt < 2; nt++) {
                    mma_tf32(acc[mi][nt * 2 + 0], aF[mi], bF[nt][0], bF[nt][1]);
                    mma_tf32(acc[mi][nt * 2 + 1], aF[mi], bF[nt][2], bF[nt][3]);
                }
        }
        __syncthreads();
    }

    // ---- epilogue ----
    int rrow = lane >> 2;
    int cquad = (lane & 3) * 2;
#pragma unroll
    for (int mi = 0; mi < 2; mi++) {
        int r0 = m0b + warp_m + mi * 16 + rrow;
#pragma unroll
        for (int ni = 0; ni < 4; ni++) {
            int col = warp_n + ni * 8 + cquad;
            float* c = acc[mi][ni];
            if (PHASE == 0) {
                float b0v = bias[col], b1v = bias[col + 1];
                if (r0 < NN) {
                    float2 v = make_float2(fmaxf(c[0] + b0v, 0.f), fmaxf(c[1] + b1v, 0.f));
                    *(float2*)&g_h[(size_t)r0 * 128 + col] = v;
                }
                if (r0 + 8 < NN) {
                    float2 v = make_float2(fmaxf(c[2] + b0v, 0.f), fmaxf(c[3] + b1v, 0.f));
                    *(float2*)&g_h[(size_t)(r0 + 8) * 128 + col] = v;
                }
            } else {
                if (r0 < NN)
                    *(float2*)&g_yz1[(size_t)r0 * 128 + col] = make_float2(c[0], c[1]);
                if (r0 + 8 < NN)
                    *(float2*)&g_yz1[(size_t)(r0 + 8) * 128 + col] = make_float2(c[2], c[3]);
            }
        }
    }
}

// ---------------- layer-1 aggregate + bias + root ----------------
// warp per node; lane handles float2; 4-deep unrolled gather.
__global__ void k_agg2(const float* __restrict__ bias, float* __restrict__ out) {
    int node = blockIdx.x * 8 + (threadIdx.x >> 5);
    int lane = threadIdx.x & 31;
    if (node >= NN) return;
    int beg = g_off[node], end = g_off[node + 1];
    float inv = 1.0f / (float)max(end - beg, 1);
    float2 a0 = make_float2(0.f, 0.f), a1 = make_float2(0.f, 0.f);
    float2 a2 = make_float2(0.f, 0.f), a3 = make_float2(0.f, 0.f);
    int e = beg;
    for (; e + 4 <= end; e += 4) {
        int s0 = g_srcs[e], s1 = g_srcs[e + 1], s2 = g_srcs[e + 2], s3 = g_srcs[e + 3];
        float2 v0 = *(const float2*)&g_yz1[(size_t)s0 * 128 + lane * 2];
        float2 v1 = *(const float2*)&g_yz1[(size_t)s1 * 128 + lane * 2];
        float2 v2 = *(const float2*)&g_yz1[(size_t)s2 * 128 + lane * 2];
        float2 v3 = *(const float2*)&g_yz1[(size_t)s3 * 128 + lane * 2];
        a0.x += v0.x; a0.y += v0.y;
        a1.x += v1.x; a1.y += v1.y;
        a2.x += v2.x; a2.y += v2.y;
        a3.x += v3.x; a3.y += v3.y;
    }
    for (; e < end; e++) {
        int s0 = g_srcs[e];
        float2 v0 = *(const float2*)&g_yz1[(size_t)s0 * 128 + lane * 2];
        a0.x += v0.x; a0.y += v0.y;
    }
    float2 z = *(const float2*)&g_yz1[(size_t)node * 128 + 64 + lane * 2];
    float2 b = *(const float2*)&bias[lane * 2];
    float2 r;
    r.x = fmaf(a0.x + a1.x + a2.x + a3.x, inv, b.x + z.x);
    r.y = fmaf(a0.y + a1.y + a2.y + a3.y, inv, b.y + z.y);
    *(float2*)&out[(size_t)node * 64 + lane * 2] = r;
}

// ---------------- launch ----------------
extern "C" void kernel_launch(void* const* d_in, const int* in_sizes, int n_in,
                              void* d_out, int out_size) {
    const float* x = (const float*)d_in[0];
    const int* ei = (const int*)d_in[1];          // int32 edge_index [2, NE]
    const float* Wl0 = (const float*)d_in[2];
    const float* bl0 = (const float*)d_in[3];
    const float* Wr0 = (const float*)d_in[4];
    const float* Wl1 = (const float*)d_in[5];
    const float* bl1 = (const float*)d_in[6];
    const float* Wr1 = (const float*)d_in[7];
    float* out = (float*)d_out;

    const int SMEM0 = (128 * 260 + 2 * 128 * 20) * 4;  // 153600 B
    const int SMEM1 = (128 * 132 + 2 * 128 * 20) * 4;  // 88064 B
    cudaFuncSetAttribute(k_gemm<0>, cudaFuncAttributeMaxDynamicSharedMemorySize, SMEM0);
    cudaFuncSetAttribute(k_gemm<1>, cudaFuncAttributeMaxDynamicSharedMemorySize, SMEM1);

    // CSR build (every launch; graph-replay safe)
    k_zero<<<(NN + 255) / 256, 256>>>();
    k_count<<<(NE + 255) / 256, 256>>>(ei);
    k_scanA<<<NPART, 1024>>>();
    k_scanB<<<1, 128>>>();
    k_scanC<<<NPART, 1024>>>();
    k_scatter<<<(NE + 255) / 256, 256>>>(ei);
    k_pack<<<(256 * 128 + 255) / 256, 256>>>(Wl0, Wr0, Wl1, Wr1);

    int mt = (NN + 127) / 128;  // 782
    // m0 = mean(x[src])
    k_aggx<<<(NN + 7) / 8, 256>>>(x);
    // h = relu(m0 @ Wl0 + x @ Wr0 + b0)
    k_gemm<0><<<mt, 512, SMEM0>>>(x, bl0);
    // yz1 = h @ [W_l1 | W_r1]
    k_gemm<1><<<mt, 512, SMEM1>>>(nullptr, nullptr);
    // out = mean_agg(y1) + b1 + z1
    k_agg2<<<(NN + 7) / 8, 256>>>(bl1, out);
}

// round 12
// speedup vs baseline: 1.0998x; 1.0998x over previous
#include <cuda_runtime.h>

#define NN 100000
#define NE 1600000
#define NPART 98   // ceil(NN/1024)

// ---------------- scratch (static device globals; no allocs) ----------------
__device__ int      g_cnt[NN];
__device__ int      g_off[NN + 1];
__device__ int      g_pos[NN];
__device__ int      g_part[NPART];
__device__ int      g_srcs[NE];
__device__ unsigned g_B0t[128 * 256];          // tf32, [n][k]; k<128: Wl0, k>=128: Wr0
__device__ unsigned g_B1t[128 * 128];          // tf32, [j][k]; j<64: Wl1 col j, j>=64: Wr1 col j-64
__device__ float    g_m0[(size_t)NN * 128];    // mean-aggregated x
__device__ float    g_h[(size_t)NN * 128];     // relu'd layer-0 output
__device__ float    g_yz1[(size_t)NN * 128];   // y1 = cols 0..63, z1 = cols 64..127

// ---------------- tf32 mma helpers ----------------
__device__ __forceinline__ unsigned f2tf32(float f) {
    unsigned r;
    asm("cvt.rna.tf32.f32 %0, %1;" : "=r"(r) : "f"(f));
    return r;
}
__device__ __forceinline__ unsigned sptr(const void* p) {
    return (unsigned)__cvta_generic_to_shared(p);
}
#define LDSM4(R, addr)                                                              \
    asm volatile("ldmatrix.sync.aligned.m8n8.x4.shared.b16 {%0,%1,%2,%3}, [%4];"    \
                 : "=r"((R)[0]), "=r"((R)[1]), "=r"((R)[2]), "=r"((R)[3])           \
                 : "r"(addr))
__device__ __forceinline__ void mma_tf32(float* c, const unsigned* a, unsigned b0, unsigned b1) {
    asm volatile(
        "mma.sync.aligned.m16n8k8.row.col.f32.tf32.tf32.f32 "
        "{%0,%1,%2,%3},{%4,%5,%6,%7},{%8,%9},{%0,%1,%2,%3};"
        : "+f"(c[0]), "+f"(c[1]), "+f"(c[2]), "+f"(c[3])
        : "r"(a[0]), "r"(a[1]), "r"(a[2]), "r"(a[3]), "r"(b0), "r"(b1));
}

// ---------------- CSR build ----------------
__global__ void k_zero() {
    int i = blockIdx.x * blockDim.x + threadIdx.x;
    if (i < NN) g_cnt[i] = 0;
}

// edge_index is int32 (JAX x64 disabled).
__global__ void k_count(const int* __restrict__ ei) {
    int e = blockIdx.x * blockDim.x + threadIdx.x;
    if (e < NE) {
        unsigned d = (unsigned)ei[NE + e];
        if (d < NN) atomicAdd(&g_cnt[d], 1);
    }
}

__global__ void k_scanA() {  // grid NPART, block 1024: block sums
    int i = blockIdx.x * 1024 + threadIdx.x;
    int v = (i < NN) ? g_cnt[i] : 0;
    __shared__ int ws[32];
    int lane = threadIdx.x & 31, w = threadIdx.x >> 5;
#pragma unroll
    for (int d = 16; d; d >>= 1) v += __shfl_down_sync(~0u, v, d);
    if (!lane) ws[w] = v;
    __syncthreads();
    if (!w) {
        int s = ws[lane];
#pragma unroll
        for (int d = 16; d; d >>= 1) s += __shfl_down_sync(~0u, s, d);
        if (!lane) g_part[blockIdx.x] = s;
    }
}

__global__ void k_scanB() {  // 1 block / 128 threads: exclusive scan of NPART partials
    int t = threadIdx.x;
    int lane = t & 31, w = t >> 5;
    int c = (t < NPART) ? g_part[t] : 0;
    int v = c;
#pragma unroll
    for (int d = 1; d < 32; d <<= 1) {
        int u = __shfl_up_sync(~0u, v, d);
        if (lane >= d) v += u;
    }
    __shared__ int ws[4];
    if (lane == 31) ws[w] = v;
    __syncthreads();
    int add = 0;
#pragma unroll
    for (int i = 0; i < 4; i++)
        if (i < w) add += ws[i];
    int incl = v + add;
    if (t < NPART) g_part[t] = incl - c;
    if (t == NPART - 1) g_off[NN] = incl;
}

__global__ void k_scanC() {  // grid NPART, block 1024: local exclusive scan + offset
    int i = blockIdx.x * 1024 + threadIdx.x;
    int c = (i < NN) ? g_cnt[i] : 0;
    int v = c;
    int lane = threadIdx.x & 31, w = threadIdx.x >> 5;
#pragma unroll
    for (int d = 1; d < 32; d <<= 1) {
        int t = __shfl_up_sync(~0u, v, d);
        if (lane >= d) v += t;
    }
    __shared__ int ws[32];
    if (lane == 31) ws[w] = v;
    __syncthreads();
    if (!w) {
        int s = ws[lane];
#pragma unroll
        for (int d = 1; d < 32; d <<= 1) {
            int t = __shfl_up_sync(~0u, s, d);
            if (lane >= d) s += t;
        }
        ws[lane] = s;
    }
    __syncthreads();
    int excl = v - c + (w ? ws[w - 1] : 0) + g_part[blockIdx.x];
    if (i < NN) {
        g_off[i] = excl;
        g_pos[i] = excl;
    }
}

__global__ void k_scatter(const int* __restrict__ ei) {
    int e = blockIdx.x * blockDim.x + threadIdx.x;
    if (e < NE) {
        unsigned d = (unsigned)ei[NE + e];
        if (d < NN) {
            int p = atomicAdd(&g_pos[d], 1);
            unsigned s = (unsigned)ei[e];
            g_srcs[p] = (s < NN) ? (int)s : 0;
        }
    }
}

// ---------------- pack weights: transposed tf32 [n][k] ----------------
__global__ void k_pack(const float* __restrict__ Wl0, const float* __restrict__ Wr0,
                       const float* __restrict__ Wl1, const float* __restrict__ Wr1) {
    int i = blockIdx.x * blockDim.x + threadIdx.x;
    if (i < 128 * 256) {  // B0t[n*256 + k]
        int n = i >> 8, k = i & 255;
        float v = (k < 128) ? Wl0[k * 128 + n] : Wr0[(k - 128) * 128 + n];
        g_B0t[i] = f2tf32(v);
    }
    if (i < 128 * 128) {  // B1t[j*128 + k]
        int j = i >> 7, k = i & 127;
        float v = (j < 64) ? Wl1[k * 64 + j] : Wr1[k * 64 + (j - 64)];
        g_B1t[i] = f2tf32(v);
    }
}

// ---------------- input-space mean aggregation: m0 = mean(x[src]) ----------------
// warp per node; lane handles float4; 4-deep unrolled gather (MLP 4).
__global__ void k_aggx(const float* __restrict__ x) {
    int node = blockIdx.x * 8 + (threadIdx.x >> 5);
    int lane = threadIdx.x & 31;
    if (node >= NN) return;
    int beg = g_off[node], end = g_off[node + 1];
    float inv = 1.0f / (float)max(end - beg, 1);
    float4 a0 = make_float4(0.f, 0.f, 0.f, 0.f);
    float4 a1 = make_float4(0.f, 0.f, 0.f, 0.f);
    float4 a2 = make_float4(0.f, 0.f, 0.f, 0.f);
    float4 a3 = make_float4(0.f, 0.f, 0.f, 0.f);
    int e = beg;
    for (; e + 4 <= end; e += 4) {
        int s0 = g_srcs[e], s1 = g_srcs[e + 1], s2 = g_srcs[e + 2], s3 = g_srcs[e + 3];
        float4 v0 = *(const float4*)&x[(size_t)s0 * 128 + lane * 4];
        float4 v1 = *(const float4*)&x[(size_t)s1 * 128 + lane * 4];
        float4 v2 = *(const float4*)&x[(size_t)s2 * 128 + lane * 4];
        float4 v3 = *(const float4*)&x[(size_t)s3 * 128 + lane * 4];
        a0.x += v0.x; a0.y += v0.y; a0.z += v0.z; a0.w += v0.w;
        a1.x += v1.x; a1.y += v1.y; a1.z += v1.z; a1.w += v1.w;
        a2.x += v2.x; a2.y += v2.y; a2.z += v2.z; a2.w += v2.w;
        a3.x += v3.x; a3.y += v3.y; a3.z += v3.z; a3.w += v3.w;
    }
    for (; e < end; e++) {
        int s0 = g_srcs[e];
        float4 v0 = *(const float4*)&x[(size_t)s0 * 128 + lane * 4];
        a0.x += v0.x; a0.y += v0.y; a0.z += v0.z; a0.w += v0.w;
    }
    float4 r;
    r.x = (a0.x + a1.x + a2.x + a3.x) * inv;
    r.y = (a0.y + a1.y + a2.y + a3.y) * inv;
    r.z = (a0.z + a1.z + a2.z + a3.z) * inv;
    r.w = (a0.w + a1.w + a2.w + a3.w) * inv;
    *(float4*)&g_m0[(size_t)node * 128 + lane * 4] = r;
}

// ---------------- tf32 tensor-core GEMM v3 (R7 config + pre-transposed B) ----------------
// BM=128, BN=128, BK=16; 256 threads = 8 warps (4m x 2n), warp tile 32x64; 2 CTA/SM.
// PHASE 0: C = concat(m0, x) @ B0t (K=256), epilogue bias+relu -> g_h
// PHASE 1: C = g_h @ B1t (K=128), plain fp32 store -> g_yz1
template <int PHASE>
__global__ __launch_bounds__(256, 2) void k_gemm(const float* __restrict__ x,
                                                 const float* __restrict__ bias) {
    const int K = (PHASE == 0) ? 256 : 128;
    const unsigned* __restrict__ Bt = (PHASE == 0) ? g_B0t : g_B1t;

    __shared__ unsigned As[128][20];
    __shared__ unsigned Bs[128][20];

    int tid = threadIdx.x;
    int lane = tid & 31;
    int wid = tid >> 5;
    int warp_m = (wid >> 1) * 32;
    int warp_n = (wid & 1) * 64;
    int m0b = blockIdx.x * 128;

    int aRow = tid >> 1;           // 0..127
    int kLo = (tid & 1) * 8;       // 0 or 8

    float acc[2][8][4];
#pragma unroll
    for (int mi = 0; mi < 2; mi++)
#pragma unroll
        for (int ni = 0; ni < 8; ni++)
#pragma unroll
            for (int q = 0; q < 4; q++) acc[mi][ni][q] = 0.f;

    int g = lane >> 3, r = lane & 7;

    for (int k0 = 0; k0 < K; k0 += 16) {
        // ---- fill As: convert fp32 A rows to tf32 (8 elems/thread) ----
        const float* __restrict__ A = (PHASE == 0) ? ((k0 < 128) ? g_m0 : x) : g_h;
        int kk = (k0 & 127) + kLo;
        int grow = m0b + aRow;
#pragma unroll
        for (int q = 0; q < 2; q++) {
            float4 av = make_float4(0.f, 0.f, 0.f, 0.f);
            if (grow < NN) av = *(const float4*)&A[(size_t)grow * 128 + kk + q * 4];
            *(uint4*)&As[aRow][kLo + q * 4] =
                make_uint4(f2tf32(av.x), f2tf32(av.y), f2tf32(av.z), f2tf32(av.w));
        }
        // ---- fill Bs: vector copy from pre-transposed tf32 B (8 elems/thread) ----
#pragma unroll
        for (int q = 0; q < 2; q++) {
            uint4 v0 = *(const uint4*)&Bt[aRow * K + k0 + kLo + q * 4];
            *(uint4*)&Bs[aRow][kLo + q * 4] = v0;
        }
        __syncthreads();

#pragma unroll
        for (int ks = 0; ks < 16; ks += 8) {
            unsigned aF[2][4], bF[4][4];
#pragma unroll
            for (int mi = 0; mi < 2; mi++) {
                int row = warp_m + mi * 16 + (g & 1) * 8 + r;
                int col = ks + (g >> 1) * 4;
                LDSM4(aF[mi], sptr(&As[row][col]));
            }
#pragma unroll
            for (int nt = 0; nt < 4; nt++) {
                int row = warp_n + nt * 16 + (g >> 1) * 8 + r;
                int col = ks + (g & 1) * 4;
                LDSM4(bF[nt], sptr(&Bs[row][col]));
            }
#pragma unroll
            for (int mi = 0; mi < 2; mi++)
#pragma unroll
                for (int nt = 0; nt < 4; nt++) {
                    mma_tf32(acc[mi][nt * 2 + 0], aF[mi], bF[nt][0], bF[nt][1]);
                    mma_tf32(acc[mi][nt * 2 + 1], aF[mi], bF[nt][2], bF[nt][3]);
                }
        }
        __syncthreads();
    }

    // ---- epilogue ----
    int rrow = lane >> 2;
    int cquad = (lane & 3) * 2;
#pragma unroll
    for (int mi = 0; mi < 2; mi++) {
        int r0 = m0b + warp_m + mi * 16 + rrow;
#pragma unroll
        for (int ni = 0; ni < 8; ni++) {
            int col = warp_n + ni * 8 + cquad;
            float* c = acc[mi][ni];
            if (PHASE == 0) {
                float b0v = bias[col], b1v = bias[col + 1];
                if (r0 < NN) {
                    float2 v = make_float2(fmaxf(c[0] + b0v, 0.f), fmaxf(c[1] + b1v, 0.f));
                    *(float2*)&g_h[(size_t)r0 * 128 + col] = v;
                }
                if (r0 + 8 < NN) {
                    float2 v = make_float2(fmaxf(c[2] + b0v, 0.f), fmaxf(c[3] + b1v, 0.f));
                    *(float2*)&g_h[(size_t)(r0 + 8) * 128 + col] = v;
                }
            } else {
                if (r0 < NN)
                    *(float2*)&g_yz1[(size_t)r0 * 128 + col] = make_float2(c[0], c[1]);
                if (r0 + 8 < NN)
                    *(float2*)&g_yz1[(size_t)(r0 + 8) * 128 + col] = make_float2(c[2], c[3]);
            }
        }
    }
}

// ---------------- layer-1 aggregate + bias + root ----------------
// warp per node; lane handles float2; 4-deep unrolled gather.
__global__ void k_agg2(const float* __restrict__ bias, float* __restrict__ out) {
    int node = blockIdx.x * 8 + (threadIdx.x >> 5);
    int lane = threadIdx.x & 31;
    if (node >= NN) return;
    int beg = g_off[node], end = g_off[node + 1];
    float inv = 1.0f / (float)max(end - beg, 1);
    float2 a0 = make_float2(0.f, 0.f), a1 = make_float2(0.f, 0.f);
    float2 a2 = make_float2(0.f, 0.f), a3 = make_float2(0.f, 0.f);
    int e = beg;
    for (; e + 4 <= end; e += 4) {
        int s0 = g_srcs[e], s1 = g_srcs[e + 1], s2 = g_srcs[e + 2], s3 = g_srcs[e + 3];
        float2 v0 = *(const float2*)&g_yz1[(size_t)s0 * 128 + lane * 2];
        float2 v1 = *(const float2*)&g_yz1[(size_t)s1 * 128 + lane * 2];
        float2 v2 = *(const float2*)&g_yz1[(size_t)s2 * 128 + lane * 2];
        float2 v3 = *(const float2*)&g_yz1[(size_t)s3 * 128 + lane * 2];
        a0.x += v0.x; a0.y += v0.y;
        a1.x += v1.x; a1.y += v1.y;
        a2.x += v2.x; a2.y += v2.y;
        a3.x += v3.x; a3.y += v3.y;
    }
    for (; e < end; e++) {
        int s0 = g_srcs[e];
        float2 v0 = *(const float2*)&g_yz1[(size_t)s0 * 128 + lane * 2];
        a0.x += v0.x; a0.y += v0.y;
    }
    float2 z = *(const float2*)&g_yz1[(size_t)node * 128 + 64 + lane * 2];
    float2 b = *(const float2*)&bias[lane * 2];
    float2 r;
    r.x = fmaf(a0.x + a1.x + a2.x + a3.x, inv, b.x + z.x);
    r.y = fmaf(a0.y + a1.y + a2.y + a3.y, inv, b.y + z.y);
    *(float2*)&out[(size_t)node * 64 + lane * 2] = r;
}

// ---------------- launch ----------------
extern "C" void kernel_launch(void* const* d_in, const int* in_sizes, int n_in,
                              void* d_out, int out_size) {
    const float* x = (const float*)d_in[0];
    const int* ei = (const int*)d_in[1];          // int32 edge_index [2, NE]
    const float* Wl0 = (const float*)d_in[2];
    const float* bl0 = (const float*)d_in[3];
    const float* Wr0 = (const float*)d_in[4];
    const float* Wl1 = (const float*)d_in[5];
    const float* bl1 = (const float*)d_in[6];
    const float* Wr1 = (const float*)d_in[7];
    float* out = (float*)d_out;

    // CSR build (every launch; graph-replay safe)
    k_zero<<<(NN + 255) / 256, 256>>>();
    k_count<<<(NE + 255) / 256, 256>>>(ei);
    k_scanA<<<NPART, 1024>>>();
    k_scanB<<<1, 128>>>();
    k_scanC<<<NPART, 1024>>>();
    k_scatter<<<(NE + 255) / 256, 256>>>(ei);
    k_pack<<<(256 * 128 + 255) / 256, 256>>>(Wl0, Wr0, Wl1, Wr1);

    int mt = (NN + 127) / 128;  // 782
    // m0 = mean(x[src])
    k_aggx<<<(NN + 7) / 8, 256>>>(x);
    // h = relu(m0 @ Wl0 + x @ Wr0 + b0)
    k_gemm<0><<<mt, 256>>>(x, bl0);
    // yz1 = h @ [W_l1 | W_r1]
    k_gemm<1><<<mt, 256>>>(nullptr, nullptr);
    // out = mean_agg(y1) + b1 + z1
    k_agg2<<<(NN + 7) / 8, 256>>>(bl1, out);
}

// round 13
// speedup vs baseline: 1.1266x; 1.0244x over previous
#include <cuda_runtime.h>
#include <cuda_fp16.h>

#define NN 100000
#define NE 1600000
#define NPART 98   // ceil(NN/1024)

// ---------------- scratch (static device globals; no allocs) ----------------
__device__ int      g_cnt[NN];
__device__ int      g_off[NN + 1];
__device__ int      g_pos[NN];
__device__ int      g_part[NPART];
__device__ int      g_srcs[NE];
__device__ unsigned g_B0t[128 * 256];          // tf32, [n][k]; k<128: Wl0, k>=128: Wr0
__device__ unsigned g_B1t[128 * 128];          // tf32, [j][k]; j<64: Wl1 col j, j>=64: Wr1 col j-64
__device__ __half   g_x16[(size_t)NN * 128];   // fp16 copy of x (gather operand)
__device__ float    g_m0[(size_t)NN * 128];    // mean-aggregated x
__device__ float    g_h[(size_t)NN * 128];     // relu'd layer-0 output
__device__ __half   g_y16[(size_t)NN * 64];    // y1 = h @ W_l1 (fp16 gather operand)
__device__ float    g_z1[(size_t)NN * 64];     // z1 = h @ W_r1 (fp32 root term)

// ---------------- tf32 mma helpers ----------------
__device__ __forceinline__ unsigned f2tf32(float f) {
    unsigned r;
    asm("cvt.rna.tf32.f32 %0, %1;" : "=r"(r) : "f"(f));
    return r;
}
__device__ __forceinline__ unsigned sptr(const void* p) {
    return (unsigned)__cvta_generic_to_shared(p);
}
#define LDSM4(R, addr)                                                              \
    asm volatile("ldmatrix.sync.aligned.m8n8.x4.shared.b16 {%0,%1,%2,%3}, [%4];"    \
                 : "=r"((R)[0]), "=r"((R)[1]), "=r"((R)[2]), "=r"((R)[3])           \
                 : "r"(addr))
__device__ __forceinline__ void mma_tf32(float* c, const unsigned* a, unsigned b0, unsigned b1) {
    asm volatile(
        "mma.sync.aligned.m16n8k8.row.col.f32.tf32.tf32.f32 "
        "{%0,%1,%2,%3},{%4,%5,%6,%7},{%8,%9},{%0,%1,%2,%3};"
        : "+f"(c[0]), "+f"(c[1]), "+f"(c[2]), "+f"(c[3])
        : "r"(a[0]), "r"(a[1]), "r"(a[2]), "r"(a[3]), "r"(b0), "r"(b1));
}

// ---------------- CSR build ----------------
__global__ void k_zero() {
    int i = blockIdx.x * blockDim.x + threadIdx.x;
    if (i < NN) g_cnt[i] = 0;
}

// edge_index is int32 (JAX x64 disabled). Fused: per-thread edge count atomic
// + 8-float x -> fp16 conversion (NE threads == NN*128/8 exactly).
__global__ void k_count(const int* __restrict__ ei, const float* __restrict__ x) {
    int e = blockIdx.x * blockDim.x + threadIdx.x;
    if (e < NE) {
        unsigned d = (unsigned)ei[NE + e];
        if (d < NN) atomicAdd(&g_cnt[d], 1);
        // fp16 conversion of x, 8 elems per thread (rides in idle issue slots)
        size_t i = (size_t)e * 8;
        float4 v0 = *(const float4*)&x[i];
        float4 v1 = *(const float4*)&x[i + 4];
        __half2 h0 = __floats2half2_rn(v0.x, v0.y);
        __half2 h1 = __floats2half2_rn(v0.z, v0.w);
        __half2 h2 = __floats2half2_rn(v1.x, v1.y);
        __half2 h3 = __floats2half2_rn(v1.z, v1.w);
        uint4 packed;
        packed.x = *(unsigned*)&h0;
        packed.y = *(unsigned*)&h1;
        packed.z = *(unsigned*)&h2;
        packed.w = *(unsigned*)&h3;
        *(uint4*)&g_x16[i] = packed;
    }
}

__global__ void k_scanA() {  // grid NPART, block 1024: block sums
    int i = blockIdx.x * 1024 + threadIdx.x;
    int v = (i < NN) ? g_cnt[i] : 0;
    __shared__ int ws[32];
    int lane = threadIdx.x & 31, w = threadIdx.x >> 5;
#pragma unroll
    for (int d = 16; d; d >>= 1) v += __shfl_down_sync(~0u, v, d);
    if (!lane) ws[w] = v;
    __syncthreads();
    if (!w) {
        int s = ws[lane];
#pragma unroll
        for (int d = 16; d; d >>= 1) s += __shfl_down_sync(~0u, s, d);
        if (!lane) g_part[blockIdx.x] = s;
    }
}

__global__ void k_scanB() {  // 1 block / 128 threads: exclusive scan of NPART partials
    int t = threadIdx.x;
    int lane = t & 31, w = t >> 5;
    int c = (t < NPART) ? g_part[t] : 0;
    int v = c;
#pragma unroll
    for (int d = 1; d < 32; d <<= 1) {
        int u = __shfl_up_sync(~0u, v, d);
        if (lane >= d) v += u;
    }
    __shared__ int ws[4];
    if (lane == 31) ws[w] = v;
    __syncthreads();
    int add = 0;
#pragma unroll
    for (int i = 0; i < 4; i++)
        if (i < w) add += ws[i];
    int incl = v + add;
    if (t < NPART) g_part[t] = incl - c;
    if (t == NPART - 1) g_off[NN] = incl;
}

__global__ void k_scanC() {  // grid NPART, block 1024: local exclusive scan + offset
    int i = blockIdx.x * 1024 + threadIdx.x;
    int c = (i < NN) ? g_cnt[i] : 0;
    int v = c;
    int lane = threadIdx.x & 31, w = threadIdx.x >> 5;
#pragma unroll
    for (int d = 1; d < 32; d <<= 1) {
        int t = __shfl_up_sync(~0u, v, d);
        if (lane >= d) v += t;
    }
    __shared__ int ws[32];
    if (lane == 31) ws[w] = v;
    __syncthreads();
    if (!w) {
        int s = ws[lane];
#pragma unroll
        for (int d = 1; d < 32; d <<= 1) {
            int t = __shfl_up_sync(~0u, s, d);
            if (lane >= d) s += t;
        }
        ws[lane] = s;
    }
    __syncthreads();
    int excl = v - c + (w ? ws[w - 1] : 0) + g_part[blockIdx.x];
    if (i < NN) {
        g_off[i] = excl;
        g_pos[i] = excl;
    }
}

__global__ void k_scatter(const int* __restrict__ ei) {
    int e = blockIdx.x * blockDim.x + threadIdx.x;
    if (e < NE) {
        unsigned d = (unsigned)ei[NE + e];
        if (d < NN) {
            int p = atomicAdd(&g_pos[d], 1);
            unsigned s = (unsigned)ei[e];
            g_srcs[p] = (s < NN) ? (int)s : 0;
        }
    }
}

// ---------------- pack weights: transposed tf32 [n][k] ----------------
__global__ void k_pack(const float* __restrict__ Wl0, const float* __restrict__ Wr0,
                       const float* __restrict__ Wl1, const float* __restrict__ Wr1) {
    int i = blockIdx.x * blockDim.x + threadIdx.x;
    if (i < 128 * 256) {  // B0t[n*256 + k]
        int n = i >> 8, k = i & 255;
        float v = (k < 128) ? Wl0[k * 128 + n] : Wr0[(k - 128) * 128 + n];
        g_B0t[i] = f2tf32(v);
    }
    if (i < 128 * 128) {  // B1t[j*128 + k]
        int j = i >> 7, k = i & 127;
        float v = (j < 64) ? Wl1[k * 64 + j] : Wr1[k * 64 + (j - 64)];
        g_B1t[i] = f2tf32(v);
    }
}

// ---------------- input-space mean aggregation: m0 = mean(x16[src]) ----------------
// warp per node; lane handles 4 cols (8B fp16); 4-deep unrolled gather (MLP 4).
__global__ void k_aggx() {
    int node = blockIdx.x * 8 + (threadIdx.x >> 5);
    int lane = threadIdx.x & 31;
    if (node >= NN) return;
    int beg = g_off[node], end = g_off[node + 1];
    float inv = 1.0f / (float)max(end - beg, 1);
    float4 a0 = make_float4(0.f, 0.f, 0.f, 0.f);
    float4 a1 = make_float4(0.f, 0.f, 0.f, 0.f);
    float4 a2 = make_float4(0.f, 0.f, 0.f, 0.f);
    float4 a3 = make_float4(0.f, 0.f, 0.f, 0.f);
    int e = beg;
    for (; e + 4 <= end; e += 4) {
        int s0 = g_srcs[e], s1 = g_srcs[e + 1], s2 = g_srcs[e + 2], s3 = g_srcs[e + 3];
        uint2 u0 = *(const uint2*)&g_x16[(size_t)s0 * 128 + lane * 4];
        uint2 u1 = *(const uint2*)&g_x16[(size_t)s1 * 128 + lane * 4];
        uint2 u2 = *(const uint2*)&g_x16[(size_t)s2 * 128 + lane * 4];
        uint2 u3 = *(const uint2*)&g_x16[(size_t)s3 * 128 + lane * 4];
        float2 p0 = __half22float2(*(__half2*)&u0.x), p1 = __half22float2(*(__half2*)&u0.y);
        float2 q0 = __half22float2(*(__half2*)&u1.x), q1 = __half22float2(*(__half2*)&u1.y);
        float2 r0 = __half22float2(*(__half2*)&u2.x), r1 = __half22float2(*(__half2*)&u2.y);
        float2 t0 = __half22float2(*(__half2*)&u3.x), t1 = __half22float2(*(__half2*)&u3.y);
        a0.x += p0.x; a0.y += p0.y; a0.z += p1.x; a0.w += p1.y;
        a1.x += q0.x; a1.y += q0.y; a1.z += q1.x; a1.w += q1.y;
        a2.x += r0.x; a2.y += r0.y; a2.z += r1.x; a2.w += r1.y;
        a3.x += t0.x; a3.y += t0.y; a3.z += t1.x; a3.w += t1.y;
    }
    for (; e < end; e++) {
        int s0 = g_srcs[e];
        uint2 u0 = *(const uint2*)&g_x16[(size_t)s0 * 128 + lane * 4];
        float2 p0 = __half22float2(*(__half2*)&u0.x), p1 = __half22float2(*(__half2*)&u0.y);
        a0.x += p0.x; a0.y += p0.y; a0.z += p1.x; a0.w += p1.y;
    }
    float4 r;
    r.x = (a0.x + a1.x + a2.x + a3.x) * inv;
    r.y = (a0.y + a1.y + a2.y + a3.y) * inv;
    r.z = (a0.z + a1.z + a2.z + a3.z) * inv;
    r.w = (a0.w + a1.w + a2.w + a3.w) * inv;
    *(float4*)&g_m0[(size_t)node * 128 + lane * 4] = r;
}

// ---------------- tf32 tensor-core GEMM (R12 config) ----------------
// BM=128, BN=128, BK=16; 256 threads = 8 warps (4m x 2n), warp tile 32x64; 2 CTA/SM.
// PHASE 0: C = concat(m0, x) @ B0t (K=256), epilogue bias+relu -> g_h
// PHASE 1: C = g_h @ B1t (K=128); warp_n==0 -> y16 (fp16), warp_n==64 -> z1 (fp32)
template <int PHASE>
__global__ __launch_bounds__(256, 2) void k_gemm(const float* __restrict__ x,
                                                 const float* __restrict__ bias) {
    const int K = (PHASE == 0) ? 256 : 128;
    const unsigned* __restrict__ Bt = (PHASE == 0) ? g_B0t : g_B1t;

    __shared__ unsigned As[128][20];
    __shared__ unsigned Bs[128][20];

    int tid = threadIdx.x;
    int lane = tid & 31;
    int wid = tid >> 5;
    int warp_m = (wid >> 1) * 32;
    int warp_n = (wid & 1) * 64;
    int m0b = blockIdx.x * 128;

    int aRow = tid >> 1;           // 0..127
    int kLo = (tid & 1) * 8;       // 0 or 8

    float acc[2][8][4];
#pragma unroll
    for (int mi = 0; mi < 2; mi++)
#pragma unroll
        for (int ni = 0; ni < 8; ni++)
#pragma unroll
            for (int q = 0; q < 4; q++) acc[mi][ni][q] = 0.f;

    int g = lane >> 3, r = lane & 7;

    for (int k0 = 0; k0 < K; k0 += 16) {
        const float* __restrict__ A = (PHASE == 0) ? ((k0 < 128) ? g_m0 : x) : g_h;
        int kk = (k0 & 127) + kLo;
        int grow = m0b + aRow;
#pragma unroll
        for (int q = 0; q < 2; q++) {
            float4 av = make_float4(0.f, 0.f, 0.f, 0.f);
            if (grow < NN) av = *(const float4*)&A[(size_t)grow * 128 + kk + q * 4];
            *(uint4*)&As[aRow][kLo + q * 4] =
                make_uint4(f2tf32(av.x), f2tf32(av.y), f2tf32(av.z), f2tf32(av.w));
        }
#pragma unroll
        for (int q = 0; q < 2; q++) {
            uint4 v0 = *(const uint4*)&Bt[aRow * K + k0 + kLo + q * 4];
            *(uint4*)&Bs[aRow][kLo + q * 4] = v0;
        }
        __syncthreads();

#pragma unroll
        for (int ks = 0; ks < 16; ks += 8) {
            unsigned aF[2][4], bF[4][4];
#pragma unroll
            for (int mi = 0; mi < 2; mi++) {
                int row = warp_m + mi * 16 + (g & 1) * 8 + r;
                int col = ks + (g >> 1) * 4;
                LDSM4(aF[mi], sptr(&As[row][col]));
            }
#pragma unroll
            for (int nt = 0; nt < 4; nt++) {
                int row = warp_n + nt * 16 + (g >> 1) * 8 + r;
                int col = ks + (g & 1) * 4;
                LDSM4(bF[nt], sptr(&Bs[row][col]));
            }
#pragma unroll
            for (int mi = 0; mi < 2; mi++)
#pragma unroll
                for (int nt = 0; nt < 4; nt++) {
                    mma_tf32(acc[mi][nt * 2 + 0], aF[mi], bF[nt][0], bF[nt][1]);
                    mma_tf32(acc[mi][nt * 2 + 1], aF[mi], bF[nt][2], bF[nt][3]);
                }
        }
        __syncthreads();
    }

    // ---- epilogue ----
    int rrow = lane >> 2;
    int cquad = (lane & 3) * 2;
#pragma unroll
    for (int mi = 0; mi < 2; mi++) {
        int r0 = m0b + warp_m + mi * 16 + rrow;
#pragma unroll
        for (int ni = 0; ni < 8; ni++) {
            int col = warp_n + ni * 8 + cquad;
            float* c = acc[mi][ni];
            if (PHASE == 0) {
                float b0v = bias[col], b1v = bias[col + 1];
                if (r0 < NN) {
                    float2 v = make_float2(fmaxf(c[0] + b0v, 0.f), fmaxf(c[1] + b1v, 0.f));
                    *(float2*)&g_h[(size_t)r0 * 128 + col] = v;
                }
                if (r0 + 8 < NN) {
                    float2 v = make_float2(fmaxf(c[2] + b0v, 0.f), fmaxf(c[3] + b1v, 0.f));
                    *(float2*)&g_h[(size_t)(r0 + 8) * 128 + col] = v;
                }
            } else if (warp_n == 0) {  // y1 columns -> fp16 gather operand
                if (r0 < NN)
                    *(__half2*)&g_y16[(size_t)r0 * 64 + col] = __floats2half2_rn(c[0], c[1]);
                if (r0 + 8 < NN)
                    *(__half2*)&g_y16[(size_t)(r0 + 8) * 64 + col] = __floats2half2_rn(c[2], c[3]);
            } else {  // z1 columns (root term) -> fp32 exact
                int zc = col - 64;
                if (r0 < NN)
                    *(float2*)&g_z1[(size_t)r0 * 64 + zc] = make_float2(c[0], c[1]);
                if (r0 + 8 < NN)
                    *(float2*)&g_z1[(size_t)(r0 + 8) * 64 + zc] = make_float2(c[2], c[3]);
            }
        }
    }
}

// ---------------- layer-1 aggregate + bias + root ----------------
// warp per node; lane handles 2 cols (4B fp16); 4-deep unrolled gather.
__global__ void k_agg2(const float* __restrict__ bias, float* __restrict__ out) {
    int node = blockIdx.x * 8 + (threadIdx.x >> 5);
    int lane = threadIdx.x & 31;
    if (node >= NN) return;
    int beg = g_off[node], end = g_off[node + 1];
    float inv = 1.0f / (float)max(end - beg, 1);
    float2 a0 = make_float2(0.f, 0.f), a1 = make_float2(0.f, 0.f);
    float2 a2 = make_float2(0.f, 0.f), a3 = make_float2(0.f, 0.f);
    int e = beg;
    for (; e + 4 <= end; e += 4) {
        int s0 = g_srcs[e], s1 = g_srcs[e + 1], s2 = g_srcs[e + 2], s3 = g_srcs[e + 3];
        float2 v0 = __half22float2(*(const __half2*)&g_y16[(size_t)s0 * 64 + lane * 2]);
        float2 v1 = __half22float2(*(const __half2*)&g_y16[(size_t)s1 * 64 + lane * 2]);
        float2 v2 = __half22float2(*(const __half2*)&g_y16[(size_t)s2 * 64 + lane * 2]);
        float2 v3 = __half22float2(*(const __half2*)&g_y16[(size_t)s3 * 64 + lane * 2]);
        a0.x += v0.x; a0.y += v0.y;
        a1.x += v1.x; a1.y += v1.y;
        a2.x += v2.x; a2.y += v2.y;
        a3.x += v3.x; a3.y += v3.y;
    }
    for (; e < end; e++) {
        int s0 = g_srcs[e];
        float2 v0 = __half22float2(*(const __half2*)&g_y16[(size_t)s0 * 64 + lane * 2]);
        a0.x += v0.x; a0.y += v0.y;
    }
    float2 z = *(const float2*)&g_z1[(size_t)node * 64 + lane * 2];
    float2 b = *(const float2*)&bias[lane * 2];
    float2 r;
    r.x = fmaf(a0.x + a1.x + a2.x + a3.x, inv, b.x + z.x);
    r.y = fmaf(a0.y + a1.y + a2.y + a3.y, inv, b.y + z.y);
    *(float2*)&out[(size_t)node * 64 + lane * 2] = r;
}

// ---------------- launch ----------------
extern "C" void kernel_launch(void* const* d_in, const int* in_sizes, int n_in,
                              void* d_out, int out_size) {
    const float* x = (const float*)d_in[0];
    const int* ei = (const int*)d_in[1];          // int32 edge_index [2, NE]
    const float* Wl0 = (const float*)d_in[2];
    const float* bl0 = (const float*)d_in[3];
    const float* Wr0 = (const float*)d_in[4];
    const float* Wl1 = (const float*)d_in[5];
    const float* bl1 = (const float*)d_in[6];
    const float* Wr1 = (const float*)d_in[7];
    float* out = (float*)d_out;

    // CSR build (every launch; graph-replay safe)
    k_zero<<<(NN + 255) / 256, 256>>>();
    k_count<<<(NE + 255) / 256, 256>>>(ei, x);   // + fused x->fp16 conversion
    k_scanA<<<NPART, 1024>>>();
    k_scanB<<<1, 128>>>();
    k_scanC<<<NPART, 1024>>>();
    k_scatter<<<(NE + 255) / 256, 256>>>(ei);
    k_pack<<<(256 * 128 + 255) / 256, 256>>>(Wl0, Wr0, Wl1, Wr1);

    int mt = (NN + 127) / 128;  // 782
    // m0 = mean(x16[src])  (fp16 gather: halved bytes, MLP 4)
    k_aggx<<<(NN + 7) / 8, 256>>>();
    // h = relu(m0 @ Wl0 + x @ Wr0 + b0)
    k_gemm<0><<<mt, 256>>>(x, bl0);
    // y16 = h @ W_l1 (fp16), z1 = h @ W_r1 (fp32)
    k_gemm<1><<<mt, 256>>>(nullptr, nullptr);
    // out = mean_agg(y16) + b1 + z1
    k_agg2<<<(NN + 7) / 8, 256>>>(bl1, out);
}